// round 3
// baseline (speedup 1.0000x reference)
#include <cuda_runtime.h>
#include <math.h>

// LearnableKalmanTracker.
//  Kernel 1 (riccati_kernel): batch-invariant covariance/gain recursion ->
//    K_t table in __device__ memory, bitwise-exact early freeze (period-1/2).
//  Kernel 2 (consumer_kernel): per-batch mean recursion + tiny MLP.
//    R3: each lane-quad processes TWO independent sequences (A and B),
//    phase-interleaved so one sequence's instructions fill the other's
//    in-order stall bubbles (SHFL/MUFU/fma-chain latency).
// H_base = [I4|0] exploited analytically.

#define T_STEPS 512
#define SEQ_PER_WARP 16          // 8 A-seqs + 8 B-seqs
#define CONS_THREADS 32          // 1 warp per block

__device__ float g_Kall[T_STEPS * 32];   // K_t (8x4) flattened

__device__ __forceinline__ float sigmoid_fast(float x) {
    return __fdividef(1.0f, 1.0f + __expf(-x));
}

// ---------------- Kernel 1: shared Riccati recursion (32 threads) ----------
__global__ void __launch_bounds__(32)
riccati_kernel(const float* __restrict__ F_diag, const float* __restrict__ F_vel,
               const float* __restrict__ q_scale, const float* __restrict__ r_scale)
{
    __shared__ float C[64], P[64], Sinv[16], Ksh[32], fdv[8], fvv[4];
    const int lane = threadIdx.x;
    const unsigned FULL = 0xffffffffu;

    if (lane < 8) fdv[lane] = fminf(fmaxf(F_diag[lane], 0.9f), 1.1f);
    if (lane < 4) fvv[lane] = 1.0f / (1.0f + expf(-F_vel[lane]));
    const float qv = expf(q_scale[0]);
    const float rv = expf(r_scale[0]);

    const int e0 = lane, e1 = lane + 32;
    C[e0] = ((e0 >> 3) == (e0 & 7)) ? 1.0f : 0.0f;
    C[e1] = ((e1 >> 3) == (e1 & 7)) ? 1.0f : 0.0f;
    __syncwarp();

    float cold1_a = C[e0], cold1_b = C[e1];
    float cold2_a = 0.f,   cold2_b = 0.f;

    for (int t = 1; t < T_STEPS; ++t) {
#pragma unroll
        for (int h = 0; h < 2; h++) {
            int e = lane + h * 32;
            int i = e >> 3, j = e & 7;
            float fdi = fdv[i], fdj = fdv[j];
            float v = fdi * fdj * C[i * 8 + j];
            if (j < 4) v += fdi * fvv[j] * C[i * 8 + j + 4];
            if (i < 4) {
                float fvi = fvv[i];
                v += fvi * fdj * C[(i + 4) * 8 + j];
                if (j < 4) v += fvi * fvv[j] * C[(i + 4) * 8 + j + 4];
            }
            if (i == j) v += qv;
            P[e] = v;
        }
        __syncwarp();

        {
            int a = (lane >> 2) & 3, b = lane & 3;
            int r0 = 0 + (0 >= a), r1 = 1 + (1 >= a), r2 = 2 + (2 >= a);
            int c0 = 0 + (0 >= b), c1 = 1 + (1 >= b), c2 = 2 + (2 >= b);
            auto S = [&](int x, int y) -> float {
                float v = P[x * 8 + y];
                return (x == y) ? v + rv : v;
            };
            float m00 = S(r0, c0), m01 = S(r0, c1), m02 = S(r0, c2);
            float m10 = S(r1, c0), m11 = S(r1, c1), m12 = S(r1, c2);
            float m20 = S(r2, c0), m21 = S(r2, c1), m22 = S(r2, c2);
            float det3 = m00 * (m11 * m22 - m12 * m21)
                       - m01 * (m10 * m22 - m12 * m20)
                       + m02 * (m10 * m21 - m11 * m20);
            float cof = ((a + b) & 1) ? -det3 : det3;
            float c0v = __shfl_sync(FULL, cof, 0);
            float c1v = __shfl_sync(FULL, cof, 4);
            float c2v = __shfl_sync(FULL, cof, 8);
            float c3v = __shfl_sync(FULL, cof, 12);
            float det = S(0, 0) * c0v + S(1, 0) * c1v + S(2, 0) * c2v + S(3, 0) * c3v;
            float idet = __fdividef(1.0f, det);
            if (lane < 16) Sinv[b * 4 + a] = cof * idet;
        }
        __syncwarp();

        {
            int i = lane >> 2, m = lane & 3;
            float kv = P[i * 8 + 0] * Sinv[0 * 4 + m]
                     + P[i * 8 + 1] * Sinv[1 * 4 + m]
                     + P[i * 8 + 2] * Sinv[2 * 4 + m]
                     + P[i * 8 + 3] * Sinv[3 * 4 + m];
            Ksh[lane] = kv;
            g_Kall[t * 32 + lane] = kv;
        }
        __syncwarp();

        float na, nb;
        {
            int i0 = e0 >> 3, j0 = e0 & 7;
            float v = P[e0];
            v -= Ksh[i0 * 4 + 0] * P[0 * 8 + j0];
            v -= Ksh[i0 * 4 + 1] * P[1 * 8 + j0];
            v -= Ksh[i0 * 4 + 2] * P[2 * 8 + j0];
            v -= Ksh[i0 * 4 + 3] * P[3 * 8 + j0];
            na = v;
            int i1 = e1 >> 3, j1 = e1 & 7;
            float u = P[e1];
            u -= Ksh[i1 * 4 + 0] * P[0 * 8 + j1];
            u -= Ksh[i1 * 4 + 1] * P[1 * 8 + j1];
            u -= Ksh[i1 * 4 + 2] * P[2 * 8 + j1];
            u -= Ksh[i1 * 4 + 3] * P[3 * 8 + j1];
            nb = u;
        }
        int conv1 = __all_sync(FULL, (na == cold1_a) && (nb == cold1_b));
        int conv2 = __all_sync(FULL, (na == cold2_a) && (nb == cold2_b)) && (t >= 3);
        cold2_a = cold1_a; cold2_b = cold1_b;
        cold1_a = na;      cold1_b = nb;
        C[e0] = na; C[e1] = nb;
        __syncwarp();

        if (conv1) {
            float kA = Ksh[lane];
            for (int u = t + 1; u < T_STEPS; ++u) g_Kall[u * 32 + lane] = kA;
            return;
        }
        if (conv2) {
            float kA = Ksh[lane];
            float kB = g_Kall[(t - 1) * 32 + lane];
            for (int u = t + 1; u < T_STEPS; ++u)
                g_Kall[u * 32 + lane] = ((u - t) & 1) ? kB : kA;
            return;
        }
    }
}

// ---------------- Kernel 2: dual-sequence interleaved consumers ------------

struct SeqSt {                    // persistent per-sequence state
    const float4* zrow;
    float4* orow;
    float4 zs1;                   // z for step s+1
    float4 kcur0, kcur1;          // K rows q, q+4 for step s
    float p[8];                   // predicted mean (replicated per lane)
    float i0, i1, i2, i3;         // innovation for step s
    float zh[4];                  // z-half of hidden preacts for step s
};

struct Scr {                      // per-step scratch
    float4 zn, kn0, kn1;
    float kk[8];
    float FA[8], FB[8];
    float zFA0, zFA1, zFA2, zFA3;
    float hh[4], zhn[4];
    float mu, rstd, w;
};

struct Cst {                      // lane constants
    float fdc[8], fvc[4];
    float smw, b2s;
    float w1v[4][8], b1v[4], g1v[4], bev[4], w2v[4];
};

#define FULLM 0xffffffffu

__device__ __forceinline__ void ph_prefetch(SeqSt& S, Scr& R, const float4* K4, int s, int q) {
    int zi = s + 2; if (zi > T_STEPS - 1) zi = T_STEPS - 1;
    R.zn = __ldg(&S.zrow[zi]);
    int ki = s + 1; if (ki > T_STEPS - 1) ki = T_STEPS - 1;
    R.kn0 = __ldg(&K4[ki * 8 + q]);
    R.kn1 = __ldg(&K4[ki * 8 + q + 4]);
}

__device__ __forceinline__ void ph_gain(SeqSt& S, Scr& R, const Cst& C) {
    float kq  = fmaf(S.kcur0.w, S.i3, fmaf(S.kcur0.z, S.i2, fmaf(S.kcur0.y, S.i1, S.kcur0.x * S.i0)));
    float kq4 = fmaf(S.kcur1.w, S.i3, fmaf(S.kcur1.z, S.i2, fmaf(S.kcur1.y, S.i1, S.kcur1.x * S.i0)));
    R.kk[0] = __shfl_sync(FULLM, kq,  0, 4);
    R.kk[1] = __shfl_sync(FULLM, kq,  1, 4);
    R.kk[2] = __shfl_sync(FULLM, kq,  2, 4);
    R.kk[3] = __shfl_sync(FULLM, kq,  3, 4);
    R.kk[4] = __shfl_sync(FULLM, kq4, 0, 4);
    R.kk[5] = __shfl_sync(FULLM, kq4, 1, 4);
    R.kk[6] = __shfl_sync(FULLM, kq4, 2, 4);
    R.kk[7] = __shfl_sync(FULLM, kq4, 3, 4);
#pragma unroll
    for (int j = 0; j < 4; j++) {
        R.FA[j]     = fmaf(C.fvc[j], S.p[j + 4],  C.fdc[j] * S.p[j]);
        R.FB[j]     = fmaf(C.fvc[j], R.kk[j + 4], C.fdc[j] * R.kk[j]);
        R.FA[j + 4] = C.fdc[j + 4] * S.p[j + 4];
        R.FB[j + 4] = C.fdc[j + 4] * R.kk[j + 4];
    }
    R.zFA0 = S.zs1.x - R.FA[0];
    R.zFA1 = S.zs1.y - R.FA[1];
    R.zFA2 = S.zs1.z - R.FA[2];
    R.zFA3 = S.zs1.w - R.FA[3];
}

__device__ __forceinline__ void ph_hidden(SeqSt& S, Scr& R, const Cst& C) {
#pragma unroll
    for (int k = 0; k < 4; k++) {
        float a = fmaf(C.w1v[k][0], S.i0, C.b1v[k]);
        a = fmaf(C.w1v[k][1], S.i1, a);
        a = fmaf(C.w1v[k][2], S.i2, a);
        a = fmaf(C.w1v[k][3], S.i3, a);
        R.hh[k] = a + S.zh[k];
    }
#pragma unroll
    for (int k = 0; k < 4; k++) {
        float c = C.w1v[k][4] * S.zs1.x;
        c = fmaf(C.w1v[k][5], S.zs1.y, c);
        c = fmaf(C.w1v[k][6], S.zs1.z, c);
        c = fmaf(C.w1v[k][7], S.zs1.w, c);
        R.zhn[k] = c;
    }
}

__device__ __forceinline__ void ph_reduce(Scr& R) {
    float s1 = (R.hh[0] + R.hh[1]) + (R.hh[2] + R.hh[3]);
    float s2 = fmaf(R.hh[0], R.hh[0], fmaf(R.hh[1], R.hh[1],
               fmaf(R.hh[2], R.hh[2], R.hh[3] * R.hh[3])));
    s1 += __shfl_xor_sync(FULLM, s1, 1, 4);
    s2 += __shfl_xor_sync(FULLM, s2, 1, 4);
    s1 += __shfl_xor_sync(FULLM, s1, 2, 4);
    s2 += __shfl_xor_sync(FULLM, s2, 2, 4);
    R.mu = s1 * 0.0625f;
    float var = fmaf(s2, 0.0625f, -R.mu * R.mu);
    R.rstd = rsqrtf(var + 1e-5f);
}

__device__ __forceinline__ void ph_tail(Scr& R, const Cst& C) {
    float tg0 = (R.hh[0] - R.mu) * C.g1v[0];
    float tg1 = (R.hh[1] - R.mu) * C.g1v[1];
    float tg2 = (R.hh[2] - R.mu) * C.g1v[2];
    float tg3 = (R.hh[3] - R.mu) * C.g1v[3];
    float n0 = fmaxf(fmaf(tg0, R.rstd, C.bev[0]), 0.f) * C.w2v[0];
    float n1 = fmaxf(fmaf(tg1, R.rstd, C.bev[1]), 0.f) * C.w2v[1];
    float n2 = fmaxf(fmaf(tg2, R.rstd, C.bev[2]), 0.f) * C.w2v[2];
    float n3 = fmaxf(fmaf(tg3, R.rstd, C.bev[3]), 0.f) * C.w2v[3];
    float y = (n0 + n1) + (n2 + n3);
    y += __shfl_xor_sync(FULLM, y, 1, 4);
    y += __shfl_xor_sync(FULLM, y, 2, 4);
    y += C.b2s;
    R.w = sigmoid_fast(y) * C.smw;
}

__device__ __forceinline__ void ph_update(SeqSt& S, Scr& R, int s, int q) {
    if (q == 0) {
        S.orow[s] = make_float4(fmaf(R.w, R.kk[0], S.p[0]), fmaf(R.w, R.kk[1], S.p[1]),
                                fmaf(R.w, R.kk[2], S.p[2]), fmaf(R.w, R.kk[3], S.p[3]));
    }
#pragma unroll
    for (int j = 0; j < 8; j++) S.p[j] = fmaf(R.w, R.FB[j], R.FA[j]);
    S.i0 = fmaf(-R.w, R.FB[0], R.zFA0);
    S.i1 = fmaf(-R.w, R.FB[1], R.zFA1);
    S.i2 = fmaf(-R.w, R.FB[2], R.zFA2);
    S.i3 = fmaf(-R.w, R.FB[3], R.zFA3);
    S.zh[0] = R.zhn[0]; S.zh[1] = R.zhn[1]; S.zh[2] = R.zhn[2]; S.zh[3] = R.zhn[3];
    S.kcur0 = R.kn0; S.kcur1 = R.kn1;
    S.zs1 = R.zn;
}

__device__ __forceinline__ void prolog(SeqSt& S, const Cst& C, const float4* K4,
                                       const float* meas, float* out, int b, int q) {
    S.zrow = (const float4*)(meas + (size_t)b * T_STEPS * 4);
    S.orow = (float4*)(out + (size_t)b * T_STEPS * 4);
    float4 z0 = __ldg(&S.zrow[0]);
    if (q == 0) S.orow[0] = z0;
    S.p[0] = C.fdc[0] * z0.x; S.p[1] = C.fdc[1] * z0.y;
    S.p[2] = C.fdc[2] * z0.z; S.p[3] = C.fdc[3] * z0.w;
    S.p[4] = 0.f; S.p[5] = 0.f; S.p[6] = 0.f; S.p[7] = 0.f;
    float4 z1 = __ldg(&S.zrow[1]);
    S.i0 = z1.x - S.p[0]; S.i1 = z1.y - S.p[1];
    S.i2 = z1.z - S.p[2]; S.i3 = z1.w - S.p[3];
#pragma unroll
    for (int k = 0; k < 4; k++) {
        float c = C.w1v[k][4] * z1.x;
        c = fmaf(C.w1v[k][5], z1.y, c);
        c = fmaf(C.w1v[k][6], z1.z, c);
        c = fmaf(C.w1v[k][7], z1.w, c);
        S.zh[k] = c;
    }
    S.kcur0 = __ldg(&K4[1 * 8 + q]);
    S.kcur1 = __ldg(&K4[1 * 8 + q + 4]);
    S.zs1 = __ldg(&S.zrow[2]);
}

__global__ void __launch_bounds__(CONS_THREADS, 1)
consumer_kernel(const float* __restrict__ meas,
                const float* __restrict__ F_diag,
                const float* __restrict__ F_vel,
                const float* __restrict__ mw,
                const float* __restrict__ W1,
                const float* __restrict__ b1,
                const float* __restrict__ g1,
                const float* __restrict__ be1,
                const float* __restrict__ W2,
                const float* __restrict__ b2,
                float* __restrict__ out)
{
    const int lane = threadIdx.x & 31;
    const int q    = lane & 3;
    const int bA   = blockIdx.x * SEQ_PER_WARP + (lane >> 2);
    const int bB   = bA + 8;

    Cst C;
#pragma unroll
    for (int i = 0; i < 8; i++) C.fdc[i] = fminf(fmaxf(F_diag[i], 0.9f), 1.1f);
#pragma unroll
    for (int i = 0; i < 4; i++) C.fvc[i] = 1.0f / (1.0f + expf(-F_vel[i]));
    C.smw = 1.0f / (1.0f + expf(-mw[0]));
    C.b2s = b2[0];
#pragma unroll
    for (int k = 0; k < 4; k++) {
        int u = 4 * q + k;
#pragma unroll
        for (int j = 0; j < 8; j++) C.w1v[k][j] = W1[u * 8 + j];
        C.b1v[k] = b1[u]; C.g1v[k] = g1[u]; C.bev[k] = be1[u]; C.w2v[k] = W2[u];
    }

    const float4* K4 = (const float4*)g_Kall;

    SeqSt A, B;
    prolog(A, C, K4, meas, out, bA, q);
    prolog(B, C, K4, meas, out, bB, q);

    for (int s = 1; s < T_STEPS; ++s) {
        Scr RA, RB;
        ph_prefetch(A, RA, K4, s, q);  ph_prefetch(B, RB, K4, s, q);
        ph_gain(A, RA, C);             ph_gain(B, RB, C);
        ph_hidden(A, RA, C);           ph_hidden(B, RB, C);
        ph_reduce(RA);                 ph_reduce(RB);
        ph_tail(RA, C);                ph_tail(RB, C);
        ph_update(A, RA, s, q);        ph_update(B, RB, s, q);
    }
}

extern "C" void kernel_launch(void* const* d_in, const int* in_sizes, int n_in,
                              void* d_out, int out_size) {
    const float* meas    = (const float*)d_in[0];
    const float* F_diag  = (const float*)d_in[1];
    const float* F_vel   = (const float*)d_in[2];
    // d_in[3] = H_base ([I4|0], exploited analytically)
    const float* q_scale = (const float*)d_in[4];
    const float* r_scale = (const float*)d_in[5];
    const float* mw      = (const float*)d_in[6];
    const float* W1      = (const float*)d_in[7];
    const float* b1      = (const float*)d_in[8];
    const float* g1      = (const float*)d_in[9];
    const float* be1     = (const float*)d_in[10];
    const float* W2      = (const float*)d_in[11];
    const float* b2      = (const float*)d_in[12];
    float* out = (float*)d_out;

    riccati_kernel<<<1, 32>>>(F_diag, F_vel, q_scale, r_scale);

    int B = in_sizes[0] / (T_STEPS * 4);           // 2048
    dim3 grid(B / SEQ_PER_WARP);                   // 128 blocks x 1 warp
    consumer_kernel<<<grid, CONS_THREADS>>>(
        meas, F_diag, F_vel, mw, W1, b1, g1, be1, W2, b2, out);
}

// round 4
// speedup vs baseline: 1.2667x; 1.2667x over previous
#include <cuda_runtime.h>
#include <math.h>

// LearnableKalmanTracker.
//  Kernel 1 (riccati_kernel): batch-invariant covariance/gain recursion ->
//    K_t table in __device__ memory, bitwise-exact early freeze (period-1/2).
//  Kernel 2 (consumer_kernel): per-batch mean recursion + tiny MLP.
//    R4: the whole step is affine in the previous confidence scalar w:
//      innov = zf - w*Fk4,  h_k = A_k + w*B_k,  p = PA + w*PB, kin = G1 + w*G2
//    so LN stats are polynomials in w (var = C0 + C1 w + C2 w^2, (h-mu)g =
//    PG + w QG). All matvecs + cross-lane reductions are OFF the serial
//    chain; the chain is only w -> var -> rsqrt -> relu tails -> 2 shfl ->
//    sigmoid -> w'. State partitioned per lane (lane q owns comps q, q+4).
// H_base = [I4|0] exploited analytically.

#define T_STEPS 512
#define FULLM 0xffffffffu

__device__ float g_Kall[T_STEPS * 32];   // K_t (8x4) flattened

__device__ __forceinline__ float sigmoid_fast(float x) {
    return __fdividef(1.0f, 1.0f + __expf(-x));
}

// ---------------- Kernel 1: shared Riccati recursion (32 threads) ----------
__global__ void __launch_bounds__(32)
riccati_kernel(const float* __restrict__ F_diag, const float* __restrict__ F_vel,
               const float* __restrict__ q_scale, const float* __restrict__ r_scale)
{
    __shared__ float C[64], P[64], Sinv[16], Ksh[32], fdv[8], fvv[4];
    const int lane = threadIdx.x;

    if (lane < 8) fdv[lane] = fminf(fmaxf(F_diag[lane], 0.9f), 1.1f);
    if (lane < 4) fvv[lane] = 1.0f / (1.0f + expf(-F_vel[lane]));
    const float qv = expf(q_scale[0]);
    const float rv = expf(r_scale[0]);

    const int e0 = lane, e1 = lane + 32;
    C[e0] = ((e0 >> 3) == (e0 & 7)) ? 1.0f : 0.0f;
    C[e1] = ((e1 >> 3) == (e1 & 7)) ? 1.0f : 0.0f;
    __syncwarp();

    float cold1_a = C[e0], cold1_b = C[e1];
    float cold2_a = 0.f,   cold2_b = 0.f;

    for (int t = 1; t < T_STEPS; ++t) {
#pragma unroll
        for (int h = 0; h < 2; h++) {
            int e = lane + h * 32;
            int i = e >> 3, j = e & 7;
            float fdi = fdv[i], fdj = fdv[j];
            float v = fdi * fdj * C[i * 8 + j];
            if (j < 4) v += fdi * fvv[j] * C[i * 8 + j + 4];
            if (i < 4) {
                float fvi = fvv[i];
                v += fvi * fdj * C[(i + 4) * 8 + j];
                if (j < 4) v += fvi * fvv[j] * C[(i + 4) * 8 + j + 4];
            }
            if (i == j) v += qv;
            P[e] = v;
        }
        __syncwarp();

        {
            int a = (lane >> 2) & 3, b = lane & 3;
            int r0 = 0 + (0 >= a), r1 = 1 + (1 >= a), r2 = 2 + (2 >= a);
            int c0 = 0 + (0 >= b), c1 = 1 + (1 >= b), c2 = 2 + (2 >= b);
            auto S = [&](int x, int y) -> float {
                float v = P[x * 8 + y];
                return (x == y) ? v + rv : v;
            };
            float m00 = S(r0, c0), m01 = S(r0, c1), m02 = S(r0, c2);
            float m10 = S(r1, c0), m11 = S(r1, c1), m12 = S(r1, c2);
            float m20 = S(r2, c0), m21 = S(r2, c1), m22 = S(r2, c2);
            float det3 = m00 * (m11 * m22 - m12 * m21)
                       - m01 * (m10 * m22 - m12 * m20)
                       + m02 * (m10 * m21 - m11 * m20);
            float cof = ((a + b) & 1) ? -det3 : det3;
            float c0v = __shfl_sync(FULLM, cof, 0);
            float c1v = __shfl_sync(FULLM, cof, 4);
            float c2v = __shfl_sync(FULLM, cof, 8);
            float c3v = __shfl_sync(FULLM, cof, 12);
            float det = S(0, 0) * c0v + S(1, 0) * c1v + S(2, 0) * c2v + S(3, 0) * c3v;
            float idet = __fdividef(1.0f, det);
            if (lane < 16) Sinv[b * 4 + a] = cof * idet;
        }
        __syncwarp();

        {
            int i = lane >> 2, m = lane & 3;
            float kv = P[i * 8 + 0] * Sinv[0 * 4 + m]
                     + P[i * 8 + 1] * Sinv[1 * 4 + m]
                     + P[i * 8 + 2] * Sinv[2 * 4 + m]
                     + P[i * 8 + 3] * Sinv[3 * 4 + m];
            Ksh[lane] = kv;
            g_Kall[t * 32 + lane] = kv;
        }
        __syncwarp();

        float na, nb;
        {
            int i0 = e0 >> 3, j0 = e0 & 7;
            float v = P[e0];
            v -= Ksh[i0 * 4 + 0] * P[0 * 8 + j0];
            v -= Ksh[i0 * 4 + 1] * P[1 * 8 + j0];
            v -= Ksh[i0 * 4 + 2] * P[2 * 8 + j0];
            v -= Ksh[i0 * 4 + 3] * P[3 * 8 + j0];
            na = v;
            int i1 = e1 >> 3, j1 = e1 & 7;
            float u = P[e1];
            u -= Ksh[i1 * 4 + 0] * P[0 * 8 + j1];
            u -= Ksh[i1 * 4 + 1] * P[1 * 8 + j1];
            u -= Ksh[i1 * 4 + 2] * P[2 * 8 + j1];
            u -= Ksh[i1 * 4 + 3] * P[3 * 8 + j1];
            nb = u;
        }
        int conv1 = __all_sync(FULLM, (na == cold1_a) && (nb == cold1_b));
        int conv2 = __all_sync(FULLM, (na == cold2_a) && (nb == cold2_b)) && (t >= 3);
        cold2_a = cold1_a; cold2_b = cold1_b;
        cold1_a = na;      cold1_b = nb;
        C[e0] = na; C[e1] = nb;
        __syncwarp();

        if (conv1) {
            float kA = Ksh[lane];
            for (int u = t + 1; u < T_STEPS; ++u) g_Kall[u * 32 + lane] = kA;
            return;
        }
        if (conv2) {
            float kA = Ksh[lane];
            float kB = g_Kall[(t - 1) * 32 + lane];
            for (int u = t + 1; u < T_STEPS; ++u)
                g_Kall[u * 32 + lane] = ((u - t) & 1) ? kB : kA;
            return;
        }
    }
}

// ---------------- Kernel 2: affine-chain consumers -------------------------

__device__ __forceinline__ float qsel(float4 v, int q) {
    float lo = (q & 1) ? v.y : v.x;
    float hi = (q & 1) ? v.w : v.z;
    return (q & 2) ? hi : lo;
}
__device__ __forceinline__ float qred(float v) {   // sum over quad
    v += __shfl_xor_sync(FULLM, v, 1, 4);
    v += __shfl_xor_sync(FULLM, v, 2, 4);
    return v;
}
__device__ __forceinline__ float dot4(float4 a, float x0, float x1, float x2, float x3) {
    return fmaf(a.w, x3, fmaf(a.z, x2, fmaf(a.y, x1, a.x * x0)));
}

__global__ void __launch_bounds__(64, 1)
consumer_kernel(const float* __restrict__ meas,
                const float* __restrict__ F_diag,
                const float* __restrict__ F_vel,
                const float* __restrict__ mw,
                const float* __restrict__ W1,
                const float* __restrict__ b1,
                const float* __restrict__ g1,
                const float* __restrict__ be1,
                const float* __restrict__ W2,
                const float* __restrict__ b2,
                float* __restrict__ out)
{
    const int lane = threadIdx.x & 31;
    const int warp = threadIdx.x >> 5;
    const int q    = lane & 3;
    const int b    = blockIdx.x * 16 + warp * 8 + (lane >> 2);

    // lane-partitioned F: lane q owns state components q and q+4
    const float fdq  = fminf(fmaxf(F_diag[q], 0.9f), 1.1f);
    const float fdq4 = fminf(fmaxf(F_diag[q + 4], 0.9f), 1.1f);
    const float fvq  = 1.0f / (1.0f + expf(-F_vel[q]));
    const float smw  = 1.0f / (1.0f + expf(-mw[0]));
    const float b2s  = b2[0];

    // lane q owns hidden units 4q..4q+3
    float w1a[4][4], w1b[4][4], b1v[4], g1v[4], bev[4], w2v[4];
#pragma unroll
    for (int k = 0; k < 4; k++) {
        int u = 4 * q + k;
#pragma unroll
        for (int j = 0; j < 4; j++) { w1a[k][j] = W1[u * 8 + j]; w1b[k][j] = W1[u * 8 + 4 + j]; }
        b1v[k] = b1[u]; g1v[k] = g1[u]; bev[k] = be1[u]; w2v[k] = W2[u];
    }

    const float4* zr = (const float4*)(meas + (size_t)b * T_STEPS * 4);
    float* outp = out + (size_t)b * T_STEPS * 4;
    const float4* K4 = (const float4*)g_Kall;

    // ---- prologue: step-1 coefficient set (no w yet -> linear parts zero) ----
    float4 z0v = __ldg(&zr[0]);
    float4 z1v = __ldg(&zr[1]);
    float z0q = qsel(z0v, q);
    outp[q] = z0q;                                  // out row 0 = z0

    float PAq = fdq * z0q, PAq4 = 0.f;              // p_1 = F m0  (m0=[z0,0])
    float PBq = 0.f, PBq4 = 0.f;

    float zfq = qsel(z1v, q) - PAq;                 // innov_1 component q
    float zf0 = __shfl_sync(FULLM, zfq, 0, 4);
    float zf1 = __shfl_sync(FULLM, zfq, 1, 4);
    float zf2 = __shfl_sync(FULLM, zfq, 2, 4);
    float zf3 = __shfl_sync(FULLM, zfq, 3, 4);

    float4 k1r0 = __ldg(&K4[1 * 8 + q]);
    float4 k1r1 = __ldg(&K4[1 * 8 + 4 + q]);
    float G1q  = dot4(k1r0, zf0, zf1, zf2, zf3);    // kin_1 (w-free)
    float G1q4 = dot4(k1r1, zf0, zf1, zf2, zf3);
    float G2q = 0.f, G2q4 = 0.f;

    float Av[4], Bv[4];
#pragma unroll
    for (int k = 0; k < 4; k++) {
        float a = fmaf(w1b[k][0], z1v.x, b1v[k]);
        a = fmaf(w1b[k][1], z1v.y, a);
        a = fmaf(w1b[k][2], z1v.z, a);
        a = fmaf(w1b[k][3], z1v.w, a);
        a = fmaf(w1a[k][0], zf0, a);
        a = fmaf(w1a[k][1], zf1, a);
        a = fmaf(w1a[k][2], zf2, a);
        a = fmaf(w1a[k][3], zf3, a);
        Av[k] = a; Bv[k] = 0.f;
    }
    float C0, C1 = 0.f, C2 = 0.f, PG[4], QG[4];
    {
        float sa  = qred((Av[0] + Av[1]) + (Av[2] + Av[3]));
        float saa = qred(fmaf(Av[0], Av[0], fmaf(Av[1], Av[1],
                     fmaf(Av[2], Av[2], Av[3] * Av[3]))));
        float mA = sa * 0.0625f;
        C0 = fmaf(-mA, mA, fmaf(saa, 0.0625f, 1e-5f));
#pragma unroll
        for (int k = 0; k < 4; k++) { PG[k] = (Av[k] - mA) * g1v[k]; QG[k] = 0.f; }
    }

    float4 kcur0 = __ldg(&K4[2 * 8 + q]);           // K_{s+1} rows for iter s=1
    float4 kcur1 = __ldg(&K4[2 * 8 + 4 + q]);
    float4 znext = __ldg(&zr[2]);                   // z_{s+1} for iter s=1
    float wprev = 0.f;

    for (int s = 1; s < T_STEPS; ++s) {
        // rolling prefetch (for iter s+1)
        int fi = s + 2; if (fi > T_STEPS - 1) fi = T_STEPS - 1;
        float4 zfut = __ldg(&zr[fi]);
        float4 kf0  = __ldg(&K4[fi * 8 + q]);
        float4 kf1  = __ldg(&K4[fi * 8 + 4 + q]);

        // ======== CHAIN: w_s from wprev and old coefficient set ========
        float wsq  = wprev * wprev;
        float var  = fmaf(C2, wsq, fmaf(C1, wprev, C0));   // includes +1e-5
        float rstd = rsqrtf(var);
        float t0 = fmaf(QG[0], wprev, PG[0]);
        float t1 = fmaf(QG[1], wprev, PG[1]);
        float t2 = fmaf(QG[2], wprev, PG[2]);
        float t3 = fmaf(QG[3], wprev, PG[3]);
        float n0 = fmaxf(fmaf(t0, rstd, bev[0]), 0.f) * w2v[0];
        float n1 = fmaxf(fmaf(t1, rstd, bev[1]), 0.f) * w2v[1];
        float n2 = fmaxf(fmaf(t2, rstd, bev[2]), 0.f) * w2v[2];
        float n3 = fmaxf(fmaf(t3, rstd, bev[3]), 0.f) * w2v[3];
        float y  = (n0 + n1) + (n2 + n3);
        y += __shfl_xor_sync(FULLM, y, 1, 4);
        y += __shfl_xor_sync(FULLM, y, 2, 4);
        float w = sigmoid_fast(y + b2s) * smw;             // w_s

        // ======== concrete state for step s (needs wprev only) ========
        float pq   = fmaf(wprev, PBq,  PAq);
        float pq4  = fmaf(wprev, PBq4, PAq4);
        float knq  = fmaf(wprev, G2q,  G1q);
        float knq4 = fmaf(wprev, G2q4, G1q4);

        // output m_s[q] (coalesced scalar store per lane)
        outp[s * 4 + q] = fmaf(w, knq, pq);

        // ======== build coefficient set for step s+1 (off-chain) ========
        float Fpq  = fmaf(fvq, pq4,  fdq * pq);            // (F p_s)
        float Fpq4 = fdq4 * pq4;
        float Fkq  = fmaf(fvq, knq4, fdq * knq);           // (F kin_s)
        float Fkq4 = fdq4 * knq4;

        float nzq = qsel(znext, q);
        float zq  = nzq - Fpq;                             // zf component q
        float z0_ = __shfl_sync(FULLM, zq, 0, 4);
        float z1_ = __shfl_sync(FULLM, zq, 1, 4);
        float z2_ = __shfl_sync(FULLM, zq, 2, 4);
        float z3_ = __shfl_sync(FULLM, zq, 3, 4);
        float g0_ = __shfl_sync(FULLM, Fkq, 0, 4);         // Fk[0..3]
        float g1_ = __shfl_sync(FULLM, Fkq, 1, 4);
        float g2_ = __shfl_sync(FULLM, Fkq, 2, 4);
        float g3_ = __shfl_sync(FULLM, Fkq, 3, 4);

        // kin_{s+1} = G1 + w_s G2
        G1q  = dot4(kcur0, z0_, z1_, z2_, z3_);
        G1q4 = dot4(kcur1, z0_, z1_, z2_, z3_);
        G2q  = -dot4(kcur0, g0_, g1_, g2_, g3_);
        G2q4 = -dot4(kcur1, g0_, g1_, g2_, g3_);
        // p_{s+1} = PA + w_s PB
        PAq = Fpq; PAq4 = Fpq4; PBq = Fkq; PBq4 = Fkq4;

        // hidden coefficients: h_k(s+1) = A_k + w_s B_k
#pragma unroll
        for (int k = 0; k < 4; k++) {
            float a = fmaf(w1b[k][0], znext.x, b1v[k]);
            a = fmaf(w1b[k][1], znext.y, a);
            a = fmaf(w1b[k][2], znext.z, a);
            a = fmaf(w1b[k][3], znext.w, a);
            a = fmaf(w1a[k][0], z0_, a);
            a = fmaf(w1a[k][1], z1_, a);
            a = fmaf(w1a[k][2], z2_, a);
            a = fmaf(w1a[k][3], z3_, a);
            Av[k] = a;
            float bb = w1a[k][0] * g0_;
            bb = fmaf(w1a[k][1], g1_, bb);
            bb = fmaf(w1a[k][2], g2_, bb);
            bb = fmaf(w1a[k][3], g3_, bb);
            Bv[k] = -bb;
        }
        // LN polynomial coefficients
        float sa  = (Av[0] + Av[1]) + (Av[2] + Av[3]);
        float sb  = (Bv[0] + Bv[1]) + (Bv[2] + Bv[3]);
        float saa = fmaf(Av[0], Av[0], fmaf(Av[1], Av[1], fmaf(Av[2], Av[2], Av[3] * Av[3])));
        float sab = fmaf(Av[0], Bv[0], fmaf(Av[1], Bv[1], fmaf(Av[2], Bv[2], Av[3] * Bv[3])));
        float sbb = fmaf(Bv[0], Bv[0], fmaf(Bv[1], Bv[1], fmaf(Bv[2], Bv[2], Bv[3] * Bv[3])));
        sa = qred(sa); sb = qred(sb); saa = qred(saa); sab = qred(sab); sbb = qred(sbb);
        float mA = sa * 0.0625f, mB = sb * 0.0625f;
        C0 = fmaf(-mA, mA, fmaf(saa, 0.0625f, 1e-5f));
        C1 = 2.0f * fmaf(-mA, mB, sab * 0.0625f);
        C2 = fmaf(-mB, mB, sbb * 0.0625f);
#pragma unroll
        for (int k = 0; k < 4; k++) {
            PG[k] = (Av[k] - mA) * g1v[k];
            QG[k] = (Bv[k] - mB) * g1v[k];
        }

        // rotate
        znext = zfut; kcur0 = kf0; kcur1 = kf1; wprev = w;
    }
}

extern "C" void kernel_launch(void* const* d_in, const int* in_sizes, int n_in,
                              void* d_out, int out_size) {
    const float* meas    = (const float*)d_in[0];
    const float* F_diag  = (const float*)d_in[1];
    const float* F_vel   = (const float*)d_in[2];
    // d_in[3] = H_base ([I4|0], exploited analytically)
    const float* q_scale = (const float*)d_in[4];
    const float* r_scale = (const float*)d_in[5];
    const float* mw      = (const float*)d_in[6];
    const float* W1      = (const float*)d_in[7];
    const float* b1      = (const float*)d_in[8];
    const float* g1      = (const float*)d_in[9];
    const float* be1     = (const float*)d_in[10];
    const float* W2      = (const float*)d_in[11];
    const float* b2      = (const float*)d_in[12];
    float* out = (float*)d_out;

    riccati_kernel<<<1, 32>>>(F_diag, F_vel, q_scale, r_scale);

    int B = in_sizes[0] / (T_STEPS * 4);           // 2048
    dim3 grid(B / 16);                             // 128 blocks x 2 warps
    consumer_kernel<<<grid, 64>>>(
        meas, F_diag, F_vel, mw, W1, b1, g1, be1, W2, b2, out);
}